// round 10
// baseline (speedup 1.0000x reference)
#include <cuda_runtime.h>
#include <cuda_bf16.h>
#include <math_constants.h>
#include <cstdint>

// Problem constants
#define NN 32768
#define KK 8192
#define DD 256
#define BETA 0.25f
#define DECAY 0.99f
#define ONE_MINUS_DECAY 0.01f
#define EPS 1e-5f
#define K_EPS 0.08192f

// Output layout (float32): z_q_st, commitment, idx, new_embed, new_count, new_avg
#define OFF_ZQ     0
#define OFF_COMMIT ((size_t)NN * DD)
#define OFF_IDX    (OFF_COMMIT + 1)
#define OFF_EMB    (OFF_IDX + NN)
#define OFF_CNT    (OFF_EMB + (size_t)KK * DD)
#define OFF_AVG    (OFF_CNT + KK)

// GEMM tiling (baseline mma.sync path — compute_103-safe)
#define BM 128
#define BN 64
#define NTILES (KK / BN)   // 128
#define MARGIN 6e-4f
#define CAP 6

// Scratch (device globals — no allocations allowed)
__device__ float g_wnorm[KK];
__device__ float g_znorm[NN];
__device__ int   g_idx[NN];
__device__ int   g_cnt[KK];
__device__ float g_cpart[NN];
__device__ float g_nsum;
__device__ __nv_bfloat16 g_zh[(size_t)NN * DD];
__device__ __nv_bfloat16 g_wh[(size_t)KK * DD];
__device__ float         g_tilemin[(size_t)NN * NTILES];
__device__ int           g_cand[(size_t)NN * NTILES * CAP];
__device__ unsigned char g_ccnt[(size_t)NN * NTILES];
__device__ unsigned char g_ovf[NN];

// ======================= baseline PTX helpers =======================
__device__ __forceinline__ uint32_t smem_u32(const void* p) {
    uint32_t a;
    asm("{ .reg .u64 t; cvta.to.shared.u64 t, %1; cvt.u32.u64 %0, t; }" : "=r"(a) : "l"(p));
    return a;
}
#define CP_ASYNC16(dst, src) \
    asm volatile("cp.async.cg.shared.global [%0], [%1], 16;" :: "r"(dst), "l"(src) : "memory")
#define CP_COMMIT() asm volatile("cp.async.commit_group;" ::: "memory")
#define CP_WAIT0()  asm volatile("cp.async.wait_group 0;" ::: "memory")
#define LDSM4(r0, r1, r2, r3, addr) \
    asm volatile("ldmatrix.sync.aligned.m8n8.x4.shared.b16 {%0,%1,%2,%3}, [%4];" \
        : "=r"(r0), "=r"(r1), "=r"(r2), "=r"(r3) : "r"(addr))
#define MMA16816(d, a0, a1, a2, a3, b0, b1) \
    asm volatile("mma.sync.aligned.m16n8k16.row.col.f32.bf16.bf16.f32 " \
        "{%0,%1,%2,%3}, {%4,%5,%6,%7}, {%8,%9}, {%0,%1,%2,%3};" \
        : "+f"((d)[0]), "+f"((d)[1]), "+f"((d)[2]), "+f"((d)[3]) \
        : "r"(a0), "r"(a1), "r"(a2), "r"(a3), "r"(b0), "r"(b1))

// Swizzled smem byte offset for (row, k-element) in a [rows][256 bf16] tile.
// Row stride 512B; 16B chunks XOR-permuted within each 128B group by row&7.
__device__ __forceinline__ uint32_t sw_off(int row, int kelem) {
    int kc = kelem >> 3;               // 16B chunk index within row (0..31)
    return (uint32_t)(row * 512 + ((kc >> 3) << 7) + (((kc & 7) ^ (row & 7)) << 4));
}

// ======================= kernel 1: exact row norms =======================
__global__ void norms_kernel(const float* __restrict__ z, const float* __restrict__ w) {
    int r = blockIdx.x * blockDim.x + threadIdx.x;
    if (r < NN) {
        const float* p = z + (size_t)r * DD;
        float s = 0.f;
        for (int i = 0; i < DD; ++i) s = __fadd_rn(s, __fmul_rn(p[i], p[i]));
        g_znorm[r] = s;
    }
    if (r < KK) {
        const float* p = w + (size_t)r * DD;
        float s = 0.f;
        for (int i = 0; i < DD; ++i) s = __fadd_rn(s, __fmul_rn(p[i], p[i]));
        g_wnorm[r] = s;
    }
}

// ======================= kernel 2: bf16 hi conversion =======================
__global__ void split_kernel(const float* __restrict__ z, const float* __restrict__ w) {
    size_t i = (size_t)blockIdx.x * blockDim.x + threadIdx.x;
    if (i < (size_t)NN * DD) g_zh[i] = __float2bfloat16(z[i]);
    if (i < (size_t)KK * DD) g_wh[i] = __float2bfloat16(w[i]);
}

// ======================= kernel 3: init =======================
__global__ void init_kernel(const float* __restrict__ ema_avg, float* __restrict__ out) {
    size_t i = (size_t)blockIdx.x * blockDim.x + threadIdx.x;
    if (i < (size_t)KK * DD) out[OFF_AVG + i] = __fmul_rn(DECAY, ema_avg[i]);
    if (i < KK) g_cnt[i] = 0;
    if (i < NN) g_ovf[i] = 0;
}

// ======================= kernel 4: mma.sync GEMM + candidate collection ==========
// SMEM: As [128][256] bf16 swizzled (64KB) | Bs [64][256] bf16 (32KB) |
//       rowmin[2][128] f32 | rowcnt[128] i32
#define SM_A 0
#define SM_B (BM * 512)                      // 65536
#define SM_RMIN (SM_B + BN * 512)            // 98304
#define SM_RCNT (SM_RMIN + 2 * BM * 4)       // 99328
#define SMEM_TOTAL (SM_RCNT + BM * 4)        // 99840

__global__ void __launch_bounds__(256, 2)
gemm_score_kernel() {
    extern __shared__ char smem[];
    uint32_t sb = smem_u32(smem);
    const int tid = threadIdx.x;
    const int lane = tid & 31, wid = tid >> 5;
    const int warpm = wid >> 1, warpn = wid & 1;
    const int ntile = blockIdx.x;    // 0..127
    const int mtile = blockIdx.y;    // 0..255
    const int mb = warpm * 32;       // CTA-local warp row base
    const int nb = warpn * 32;       // CTA-local warp col base

    float* rm = reinterpret_cast<float*>(smem + SM_RMIN);   // [2][BM]
    int*   rc = reinterpret_cast<int*>(smem + SM_RCNT);     // [BM]
    if (tid < 2 * BM) rm[tid] = CUDART_INF_F;
    if (tid < BM) rc[tid] = 0;

    // ---- async stage A (128x256) and B (64x256) bf16 into swizzled smem ----
    const __nv_bfloat16* gA = g_zh + (size_t)(mtile * BM) * DD;
    const __nv_bfloat16* gB = g_wh + (size_t)(ntile * BN) * DD;
    #pragma unroll
    for (int i = 0; i < 16; ++i) {
        int lin = tid + i * 256;
        int r = lin >> 5, kc = lin & 31;
        CP_ASYNC16(sb + SM_A + r * 512 + ((kc >> 3) << 7) + (((kc & 7) ^ (r & 7)) << 4),
                   gA + (size_t)r * DD + kc * 8);
    }
    #pragma unroll
    for (int i = 0; i < 8; ++i) {
        int lin = tid + i * 256;
        int r = lin >> 5, kc = lin & 31;
        CP_ASYNC16(sb + SM_B + r * 512 + ((kc >> 3) << 7) + (((kc & 7) ^ (r & 7)) << 4),
                   gB + (size_t)r * DD + kc * 8);
    }
    CP_COMMIT();
    CP_WAIT0();
    __syncthreads();

    // ---- mainloop: 16 k-steps of m32 x n32 x k16 per warp ----
    float acc[2][4][4];
    #pragma unroll
    for (int ms = 0; ms < 2; ++ms)
        #pragma unroll
        for (int ns = 0; ns < 4; ++ns)
            #pragma unroll
            for (int j = 0; j < 4; ++j) acc[ms][ns][j] = 0.f;

    const int arow = mb + (lane & 7) + ((lane >> 3) & 1) * 8;
    const int brow = nb + (lane & 7) + (lane >> 4) * 8;
    #pragma unroll
    for (int ks = 0; ks < 16; ++ks) {
        const int ak = ks * 16 + (lane >> 4) * 8;
        const int bk = ks * 16 + ((lane >> 3) & 1) * 8;
        uint32_t a0, a1, a2, a3, a4, a5, a6, a7;
        uint32_t b0, b1, b2, b3, b4, b5, b6, b7;
        LDSM4(a0, a1, a2, a3, sb + SM_A + sw_off(arow, ak));
        LDSM4(a4, a5, a6, a7, sb + SM_A + sw_off(arow + 16, ak));
        LDSM4(b0, b1, b2, b3, sb + SM_B + sw_off(brow, bk));
        LDSM4(b4, b5, b6, b7, sb + SM_B + sw_off(brow + 16, bk));
        MMA16816(acc[0][0], a0, a1, a2, a3, b0, b1);
        MMA16816(acc[0][1], a0, a1, a2, a3, b2, b3);
        MMA16816(acc[0][2], a0, a1, a2, a3, b4, b5);
        MMA16816(acc[0][3], a0, a1, a2, a3, b6, b7);
        MMA16816(acc[1][0], a4, a5, a6, a7, b0, b1);
        MMA16816(acc[1][1], a4, a5, a6, a7, b2, b3);
        MMA16816(acc[1][2], a4, a5, a6, a7, b4, b5);
        MMA16816(acc[1][3], a4, a5, a6, a7, b6, b7);
    }

    // ---- epilogue pass 1: per-row minima of approx scores s = wn - 2*dot ----
    const float* wn = g_wnorm + ntile * BN;
    float wnv[4][2];
    #pragma unroll
    for (int ns = 0; ns < 4; ++ns) {
        int c0 = nb + ns * 8 + (lane & 3) * 2;
        wnv[ns][0] = wn[c0];
        wnv[ns][1] = wn[c0 + 1];
    }
    float rmn[2][2] = {{CUDART_INF_F, CUDART_INF_F}, {CUDART_INF_F, CUDART_INF_F}};
    #pragma unroll
    for (int ms = 0; ms < 2; ++ms)
        #pragma unroll
        for (int ns = 0; ns < 4; ++ns) {
            float s0 = fmaf(-2.f, acc[ms][ns][0], wnv[ns][0]);
            float s1 = fmaf(-2.f, acc[ms][ns][1], wnv[ns][1]);
            float s2 = fmaf(-2.f, acc[ms][ns][2], wnv[ns][0]);
            float s3 = fmaf(-2.f, acc[ms][ns][3], wnv[ns][1]);
            rmn[ms][0] = fminf(rmn[ms][0], fminf(s0, s1));
            rmn[ms][1] = fminf(rmn[ms][1], fminf(s2, s3));
        }
    #pragma unroll
    for (int ms = 0; ms < 2; ++ms)
        #pragma unroll
        for (int h = 0; h < 2; ++h) {
            float v = rmn[ms][h];
            v = fminf(v, __shfl_xor_sync(0xffffffffu, v, 1));
            v = fminf(v, __shfl_xor_sync(0xffffffffu, v, 2));
            if ((lane & 3) == 0)
                rm[warpn * BM + mb + ms * 16 + h * 8 + (lane >> 2)] = v;
        }
    __syncthreads();

    // ---- epilogue pass 2: collect candidates within MARGIN of row min ----
    #pragma unroll
    for (int ms = 0; ms < 2; ++ms)
        #pragma unroll
        for (int ns = 0; ns < 4; ++ns)
            #pragma unroll
            for (int j = 0; j < 4; ++j) {
                int lr = mb + ms * 16 + ((j >> 1) << 3) + (lane >> 2);
                float thr = fminf(rm[lr], rm[BM + lr]) + MARGIN;
                float sv = fmaf(-2.f, acc[ms][ns][j], wnv[ns][j & 1]);
                if (sv <= thr) {
                    int pos = atomicAdd(&rc[lr], 1);
                    if (pos < CAP) {
                        int col = ntile * BN + nb + ns * 8 + (lane & 3) * 2 + (j & 1);
                        g_cand[((size_t)(mtile * BM + lr) * NTILES + ntile) * CAP + pos] = col;
                    }
                }
            }
    __syncthreads();

    if (tid < BM) {
        int row = mtile * BM + tid;
        int c = rc[tid];
        if (c > CAP) { g_ovf[row] = 1; c = CAP; }
        g_ccnt[(size_t)row * NTILES + ntile] = (unsigned char)c;
        g_tilemin[(size_t)row * NTILES + ntile] = fminf(rm[tid], rm[BM + tid]);
    }
}

// ======================= kernel 5: exact rescore + argmin =======================
__device__ __forceinline__ float exact_dist(const float* __restrict__ zr,
                                            const float* __restrict__ w,
                                            float zn, int k) {
    const float* wr = w + (size_t)k * DD;
    float dot = 0.f;
    #pragma unroll 8
    for (int i = 0; i < DD; ++i) dot = __fmaf_rn(zr[i], wr[i], dot);
    return __fadd_rn(__fsub_rn(zn, 2.0f * dot), g_wnorm[k]);
}

__global__ void rescore_kernel(const float* __restrict__ z, const float* __restrict__ w,
                               float* __restrict__ out) {
    int gw = (blockIdx.x * blockDim.x + threadIdx.x) >> 5;
    int lane = threadIdx.x & 31;
    if (gw >= NN) return;
    int n = gw;
    float tmv[4];
    #pragma unroll
    for (int j = 0; j < 4; ++j)
        tmv[j] = g_tilemin[(size_t)n * NTILES + lane + 32 * j];
    float gmin = fminf(fminf(tmv[0], tmv[1]), fminf(tmv[2], tmv[3]));
    #pragma unroll
    for (int o = 16; o > 0; o >>= 1) gmin = fminf(gmin, __shfl_xor_sync(0xffffffffu, gmin, o));
    float zn = g_znorm[n];
    const float* zr = z + (size_t)n * DD;
    float bv = CUDART_INF_F;
    int bi = 0x7fffffff;
    if (g_ovf[n]) {
        for (int k = lane; k < KK; k += 32) {
            float d = exact_dist(zr, w, zn, k);
            if (d < bv || (d == bv && k < bi)) { bv = d; bi = k; }
        }
    } else {
        float thr = gmin + MARGIN;
        #pragma unroll
        for (int j = 0; j < 4; ++j) {
            if (tmv[j] <= thr) {
                int t = lane + 32 * j;
                int c = g_ccnt[(size_t)n * NTILES + t];
                size_t cbase = ((size_t)n * NTILES + t) * CAP;
                for (int q = 0; q < c; ++q) {
                    int k = g_cand[cbase + q];
                    float d = exact_dist(zr, w, zn, k);
                    if (d < bv || (d == bv && k < bi)) { bv = d; bi = k; }
                }
            }
        }
    }
    #pragma unroll
    for (int o = 16; o > 0; o >>= 1) {
        float ov = __shfl_down_sync(0xffffffffu, bv, o);
        int   oi = __shfl_down_sync(0xffffffffu, bi, o);
        if (ov < bv || (ov == bv && oi < bi)) { bv = ov; bi = oi; }
    }
    if (lane == 0) {
        g_idx[n] = bi;
        out[OFF_IDX + n] = (float)bi;
    }
}

// ======================= kernel 6: gather + commitment + EMA scatter ===========
__global__ void gather_kernel(const float* __restrict__ z, const float* __restrict__ w,
                              float* __restrict__ out) {
    int n = blockIdx.x;
    int d = threadIdx.x;  // 256
    int k = g_idx[n];
    float ze = z[(size_t)n * DD + d];
    float wv = w[(size_t)k * DD + d];
    out[OFF_ZQ + (size_t)n * DD + d] = __fadd_rn(ze, __fsub_rn(wv, ze));
    float diff = __fsub_rn(ze, wv);
    float s = __fmul_rn(diff, diff);
    __shared__ float red[8];
    #pragma unroll
    for (int o = 16; o > 0; o >>= 1) s += __shfl_down_sync(0xffffffffu, s, o);
    if ((threadIdx.x & 31) == 0) red[threadIdx.x >> 5] = s;
    __syncthreads();
    if (threadIdx.x == 0) {
        float t = 0.f;
        #pragma unroll
        for (int i = 0; i < 8; i++) t += red[i];
        g_cpart[n] = t;
        atomicAdd(&g_cnt[k], 1);
    }
    atomicAdd(&out[OFF_AVG + (size_t)k * DD + d], __fmul_rn(ONE_MINUS_DECAY, ze));
}

// ======================= kernel 7: new_count =======================
__global__ void count_kernel(const float* __restrict__ ema_count, float* __restrict__ out) {
    int k = blockIdx.x * blockDim.x + threadIdx.x;
    if (k >= KK) return;
    out[OFF_CNT + k] = __fadd_rn(__fmul_rn(DECAY, ema_count[k]),
                                 __fmul_rn(ONE_MINUS_DECAY, (float)g_cnt[k]));
}

// ======================= kernel 8: reductions =======================
__global__ void finalize_kernel(float* __restrict__ out) {
    __shared__ float sh[1024];
    int t = threadIdx.x;
    float s = 0.f;
    for (int i = t; i < NN; i += 1024) s += g_cpart[i];
    sh[t] = s;
    __syncthreads();
    for (int o = 512; o > 0; o >>= 1) {
        if (t < o) sh[t] += sh[t + o];
        __syncthreads();
    }
    if (t == 0) {
        float mean = __fdiv_rn(sh[0], (float)((size_t)NN * DD));
        out[OFF_COMMIT] = __fmul_rn(BETA, mean);
    }
    __syncthreads();
    float c = 0.f;
    for (int i = t; i < KK; i += 1024) c += out[OFF_CNT + i];
    sh[t] = c;
    __syncthreads();
    for (int o = 512; o > 0; o >>= 1) {
        if (t < o) sh[t] += sh[t + o];
        __syncthreads();
    }
    if (t == 0) g_nsum = sh[0];
}

// ======================= kernel 9: new_embed =======================
__global__ void embed_kernel(float* __restrict__ out) {
    size_t i = (size_t)blockIdx.x * blockDim.x + threadIdx.x;
    if (i >= (size_t)KK * DD) return;
    int k = (int)(i / DD);
    float n = g_nsum;
    float cnt = out[OFF_CNT + k];
    float cs = __fmul_rn(__fdiv_rn(__fadd_rn(cnt, EPS), __fadd_rn(n, K_EPS)), n);
    out[OFF_EMB + i] = __fdiv_rn(out[OFF_AVG + i], cs);
}

// ======================= launch =======================
extern "C" void kernel_launch(void* const* d_in, const int* in_sizes, int n_in,
                              void* d_out, int out_size) {
    const float* z  = (const float*)d_in[0];
    const float* w  = (const float*)d_in[1];
    const float* ec = (const float*)d_in[2];
    const float* ea = (const float*)d_in[3];
    float* out = (float*)d_out;

    cudaFuncSetAttribute(gemm_score_kernel, cudaFuncAttributeMaxDynamicSharedMemorySize,
                         SMEM_TOTAL);

    norms_kernel<<<NN / 256, 256>>>(z, w);
    split_kernel<<<(NN * DD + 255) / 256, 256>>>(z, w);
    init_kernel<<<(KK * DD + 255) / 256, 256>>>(ea, out);
    dim3 grid(NTILES, NN / BM);   // 128 x 256
    gemm_score_kernel<<<grid, 256, SMEM_TOTAL>>>();
    rescore_kernel<<<(NN * 32 + 255) / 256, 256>>>(z, w, out);
    gather_kernel<<<NN, 256>>>(z, w, out);
    count_kernel<<<KK / 256, 256>>>(ec, out);
    finalize_kernel<<<1, 1024>>>(out);
    embed_kernel<<<(KK * DD + 255) / 256, 256>>>(out);
    (void)in_sizes; (void)n_in; (void)out_size;
}

// round 11
// speedup vs baseline: 109.0733x; 109.0733x over previous
#include <cuda_runtime.h>
#include <cuda_bf16.h>
#include <math_constants.h>
#include <cstdint>

// Problem constants
#define NN 32768
#define KK 8192
#define DD 256
#define BETA 0.25f
#define DECAY 0.99f
#define ONE_MINUS_DECAY 0.01f
#define EPS 1e-5f
#define K_EPS 0.08192f

// Output layout (float32): z_q_st, commitment, idx, new_embed, new_count, new_avg
#define OFF_ZQ     0
#define OFF_COMMIT ((size_t)NN * DD)
#define OFF_IDX    (OFF_COMMIT + 1)
#define OFF_EMB    (OFF_IDX + NN)
#define OFF_CNT    (OFF_EMB + (size_t)KK * DD)
#define OFF_AVG    (OFF_CNT + KK)

// GEMM tiling (baseline mma.sync path — compute_103-safe)
#define BM 128
#define BN 64
#define NTILES (KK / BN)   // 128
#define MARGIN 6e-4f
#define CAP 8

// Scratch (device globals — no allocations allowed)
__device__ float g_wnorm[KK];
__device__ float g_znorm[NN];
__device__ int   g_idx[NN];
__device__ int   g_cnt[KK];
__device__ float g_cpart[NN];
__device__ float g_nsum;
__device__ __nv_bfloat16 g_zh[(size_t)NN * DD];
__device__ __nv_bfloat16 g_wh[(size_t)KK * DD];
__device__ float         g_tilemin[(size_t)NN * NTILES];
__device__ int           g_cand[(size_t)NN * NTILES * CAP];
__device__ unsigned char g_ccnt[(size_t)NN * NTILES];   // RAW count (saturated 255)

// ======================= baseline PTX helpers =======================
__device__ __forceinline__ uint32_t smem_u32(const void* p) {
    uint32_t a;
    asm("{ .reg .u64 t; cvta.to.shared.u64 t, %1; cvt.u32.u64 %0, t; }" : "=r"(a) : "l"(p));
    return a;
}
#define CP_ASYNC16(dst, src) \
    asm volatile("cp.async.cg.shared.global [%0], [%1], 16;" :: "r"(dst), "l"(src) : "memory")
#define CP_COMMIT() asm volatile("cp.async.commit_group;" ::: "memory")
#define CP_WAIT0()  asm volatile("cp.async.wait_group 0;" ::: "memory")
#define LDSM4(r0, r1, r2, r3, addr) \
    asm volatile("ldmatrix.sync.aligned.m8n8.x4.shared.b16 {%0,%1,%2,%3}, [%4];" \
        : "=r"(r0), "=r"(r1), "=r"(r2), "=r"(r3) : "r"(addr))
#define MMA16816(d, a0, a1, a2, a3, b0, b1) \
    asm volatile("mma.sync.aligned.m16n8k16.row.col.f32.bf16.bf16.f32 " \
        "{%0,%1,%2,%3}, {%4,%5,%6,%7}, {%8,%9}, {%0,%1,%2,%3};" \
        : "+f"((d)[0]), "+f"((d)[1]), "+f"((d)[2]), "+f"((d)[3]) \
        : "r"(a0), "r"(a1), "r"(a2), "r"(a3), "r"(b0), "r"(b1))

// Swizzled smem byte offset for (row, k-element) in a [rows][256 bf16] tile.
__device__ __forceinline__ uint32_t sw_off(int row, int kelem) {
    int kc = kelem >> 3;
    return (uint32_t)(row * 512 + ((kc >> 3) << 7) + (((kc & 7) ^ (row & 7)) << 4));
}

// ======================= kernel 1: exact row norms =======================
__global__ void norms_kernel(const float* __restrict__ z, const float* __restrict__ w) {
    int r = blockIdx.x * blockDim.x + threadIdx.x;
    if (r < NN) {
        const float* p = z + (size_t)r * DD;
        float s = 0.f;
        for (int i = 0; i < DD; ++i) s = __fadd_rn(s, __fmul_rn(p[i], p[i]));
        g_znorm[r] = s;
    }
    if (r < KK) {
        const float* p = w + (size_t)r * DD;
        float s = 0.f;
        for (int i = 0; i < DD; ++i) s = __fadd_rn(s, __fmul_rn(p[i], p[i]));
        g_wnorm[r] = s;
    }
}

// ======================= kernel 2: bf16 hi conversion =======================
__global__ void split_kernel(const float* __restrict__ z, const float* __restrict__ w) {
    size_t i = (size_t)blockIdx.x * blockDim.x + threadIdx.x;
    if (i < (size_t)NN * DD) g_zh[i] = __float2bfloat16(z[i]);
    if (i < (size_t)KK * DD) g_wh[i] = __float2bfloat16(w[i]);
}

// ======================= kernel 3: init =======================
__global__ void init_kernel(const float* __restrict__ ema_avg, float* __restrict__ out) {
    size_t i = (size_t)blockIdx.x * blockDim.x + threadIdx.x;
    if (i < (size_t)KK * DD) out[OFF_AVG + i] = __fmul_rn(DECAY, ema_avg[i]);
    if (i < KK) g_cnt[i] = 0;
}

// ======================= kernel 4: mma.sync GEMM + candidate collection ==========
#define SM_A 0
#define SM_B (BM * 512)                      // 65536
#define SM_RMIN (SM_B + BN * 512)            // 98304
#define SM_RCNT (SM_RMIN + 2 * BM * 4)       // 99328
#define SMEM_TOTAL (SM_RCNT + BM * 4)        // 99840

__global__ void __launch_bounds__(256, 2)
gemm_score_kernel() {
    extern __shared__ char smem[];
    uint32_t sb = smem_u32(smem);
    const int tid = threadIdx.x;
    const int lane = tid & 31, wid = tid >> 5;
    const int warpm = wid >> 1, warpn = wid & 1;
    const int ntile = blockIdx.x;
    const int mtile = blockIdx.y;
    const int mb = warpm * 32;
    const int nb = warpn * 32;

    float* rm = reinterpret_cast<float*>(smem + SM_RMIN);
    int*   rc = reinterpret_cast<int*>(smem + SM_RCNT);
    if (tid < 2 * BM) rm[tid] = CUDART_INF_F;
    if (tid < BM) rc[tid] = 0;

    const __nv_bfloat16* gA = g_zh + (size_t)(mtile * BM) * DD;
    const __nv_bfloat16* gB = g_wh + (size_t)(ntile * BN) * DD;
    #pragma unroll
    for (int i = 0; i < 16; ++i) {
        int lin = tid + i * 256;
        int r = lin >> 5, kc = lin & 31;
        CP_ASYNC16(sb + SM_A + r * 512 + ((kc >> 3) << 7) + (((kc & 7) ^ (r & 7)) << 4),
                   gA + (size_t)r * DD + kc * 8);
    }
    #pragma unroll
    for (int i = 0; i < 8; ++i) {
        int lin = tid + i * 256;
        int r = lin >> 5, kc = lin & 31;
        CP_ASYNC16(sb + SM_B + r * 512 + ((kc >> 3) << 7) + (((kc & 7) ^ (r & 7)) << 4),
                   gB + (size_t)r * DD + kc * 8);
    }
    CP_COMMIT();
    CP_WAIT0();
    __syncthreads();

    float acc[2][4][4];
    #pragma unroll
    for (int ms = 0; ms < 2; ++ms)
        #pragma unroll
        for (int ns = 0; ns < 4; ++ns)
            #pragma unroll
            for (int j = 0; j < 4; ++j) acc[ms][ns][j] = 0.f;

    const int arow = mb + (lane & 7) + ((lane >> 3) & 1) * 8;
    const int brow = nb + (lane & 7) + (lane >> 4) * 8;
    #pragma unroll
    for (int ks = 0; ks < 16; ++ks) {
        const int ak = ks * 16 + (lane >> 4) * 8;
        const int bk = ks * 16 + ((lane >> 3) & 1) * 8;
        uint32_t a0, a1, a2, a3, a4, a5, a6, a7;
        uint32_t b0, b1, b2, b3, b4, b5, b6, b7;
        LDSM4(a0, a1, a2, a3, sb + SM_A + sw_off(arow, ak));
        LDSM4(a4, a5, a6, a7, sb + SM_A + sw_off(arow + 16, ak));
        LDSM4(b0, b1, b2, b3, sb + SM_B + sw_off(brow, bk));
        LDSM4(b4, b5, b6, b7, sb + SM_B + sw_off(brow + 16, bk));
        MMA16816(acc[0][0], a0, a1, a2, a3, b0, b1);
        MMA16816(acc[0][1], a0, a1, a2, a3, b2, b3);
        MMA16816(acc[0][2], a0, a1, a2, a3, b4, b5);
        MMA16816(acc[0][3], a0, a1, a2, a3, b6, b7);
        MMA16816(acc[1][0], a4, a5, a6, a7, b0, b1);
        MMA16816(acc[1][1], a4, a5, a6, a7, b2, b3);
        MMA16816(acc[1][2], a4, a5, a6, a7, b4, b5);
        MMA16816(acc[1][3], a4, a5, a6, a7, b6, b7);
    }

    // pass 1: per-row minima
    const float* wn = g_wnorm + ntile * BN;
    float wnv[4][2];
    #pragma unroll
    for (int ns = 0; ns < 4; ++ns) {
        int c0 = nb + ns * 8 + (lane & 3) * 2;
        wnv[ns][0] = wn[c0];
        wnv[ns][1] = wn[c0 + 1];
    }
    float rmn[2][2] = {{CUDART_INF_F, CUDART_INF_F}, {CUDART_INF_F, CUDART_INF_F}};
    #pragma unroll
    for (int ms = 0; ms < 2; ++ms)
        #pragma unroll
        for (int ns = 0; ns < 4; ++ns) {
            float s0 = fmaf(-2.f, acc[ms][ns][0], wnv[ns][0]);
            float s1 = fmaf(-2.f, acc[ms][ns][1], wnv[ns][1]);
            float s2 = fmaf(-2.f, acc[ms][ns][2], wnv[ns][0]);
            float s3 = fmaf(-2.f, acc[ms][ns][3], wnv[ns][1]);
            rmn[ms][0] = fminf(rmn[ms][0], fminf(s0, s1));
            rmn[ms][1] = fminf(rmn[ms][1], fminf(s2, s3));
        }
    #pragma unroll
    for (int ms = 0; ms < 2; ++ms)
        #pragma unroll
        for (int h = 0; h < 2; ++h) {
            float v = rmn[ms][h];
            v = fminf(v, __shfl_xor_sync(0xffffffffu, v, 1));
            v = fminf(v, __shfl_xor_sync(0xffffffffu, v, 2));
            if ((lane & 3) == 0)
                rm[warpn * BM + mb + ms * 16 + h * 8 + (lane >> 2)] = v;
        }
    __syncthreads();

    // pass 2: collect candidates within MARGIN of row min (count raw)
    #pragma unroll
    for (int ms = 0; ms < 2; ++ms)
        #pragma unroll
        for (int ns = 0; ns < 4; ++ns)
            #pragma unroll
            for (int j = 0; j < 4; ++j) {
                int lr = mb + ms * 16 + ((j >> 1) << 3) + (lane >> 2);
                float thr = fminf(rm[lr], rm[BM + lr]) + MARGIN;
                float sv = fmaf(-2.f, acc[ms][ns][j], wnv[ns][j & 1]);
                if (sv <= thr) {
                    int pos = atomicAdd(&rc[lr], 1);
                    if (pos < CAP) {
                        int col = ntile * BN + nb + ns * 8 + (lane & 3) * 2 + (j & 1);
                        g_cand[((size_t)(mtile * BM + lr) * NTILES + ntile) * CAP + pos] = col;
                    }
                }
            }
    __syncthreads();

    if (tid < BM) {
        int row = mtile * BM + tid;
        int c = rc[tid];
        g_ccnt[(size_t)row * NTILES + ntile] = (unsigned char)(c > 255 ? 255 : c);
        g_tilemin[(size_t)row * NTILES + ntile] = fminf(rm[tid], rm[BM + tid]);
    }
}

// ======================= kernel 5: exact rescore + argmin =======================
__device__ __forceinline__ float exact_dist(const float* __restrict__ zr,
                                            const float* __restrict__ w,
                                            float zn, int k) {
    const float* wr = w + (size_t)k * DD;
    float dot = 0.f;
    #pragma unroll 8
    for (int i = 0; i < DD; ++i) dot = __fmaf_rn(zr[i], wr[i], dot);
    return __fadd_rn(__fsub_rn(zn, 2.0f * dot), g_wnorm[k]);
}

__global__ void rescore_kernel(const float* __restrict__ z, const float* __restrict__ w,
                               float* __restrict__ out) {
    int gw = (blockIdx.x * blockDim.x + threadIdx.x) >> 5;
    int lane = threadIdx.x & 31;
    if (gw >= NN) return;
    int n = gw;
    float tmv[4];
    #pragma unroll
    for (int j = 0; j < 4; ++j)
        tmv[j] = g_tilemin[(size_t)n * NTILES + lane + 32 * j];
    float gmin = fminf(fminf(tmv[0], tmv[1]), fminf(tmv[2], tmv[3]));
    #pragma unroll
    for (int o = 16; o > 0; o >>= 1) gmin = fminf(gmin, __shfl_xor_sync(0xffffffffu, gmin, o));
    float zn = g_znorm[n];
    const float* zr = z + (size_t)n * DD;
    float bv = CUDART_INF_F;
    int bi = 0x7fffffff;
    float thr = gmin + MARGIN;
    #pragma unroll
    for (int j = 0; j < 4; ++j) {
        if (tmv[j] <= thr) {
            int t = lane + 32 * j;
            int c = g_ccnt[(size_t)n * NTILES + t];
            if (c <= CAP) {
                // complete candidate list for this tile
                size_t cbase = ((size_t)n * NTILES + t) * CAP;
                for (int q = 0; q < c; ++q) {
                    int k = g_cand[cbase + q];
                    float d = exact_dist(zr, w, zn, k);
                    if (d < bv || (d == bv && k < bi)) { bv = d; bi = k; }
                }
            } else {
                // overflowed tile: exact rescan of its 64 columns (bounded)
                int k0 = t * BN;
                for (int k = k0; k < k0 + BN; ++k) {
                    float d = exact_dist(zr, w, zn, k);
                    if (d < bv || (d == bv && k < bi)) { bv = d; bi = k; }
                }
            }
        }
    }
    #pragma unroll
    for (int o = 16; o > 0; o >>= 1) {
        float ov = __shfl_down_sync(0xffffffffu, bv, o);
        int   oi = __shfl_down_sync(0xffffffffu, bi, o);
        if (ov < bv || (ov == bv && oi < bi)) { bv = ov; bi = oi; }
    }
    if (lane == 0) {
        g_idx[n] = bi;
        out[OFF_IDX + n] = (float)bi;
    }
}

// ======================= kernel 6: gather + commitment + EMA scatter ===========
__global__ void gather_kernel(const float* __restrict__ z, const float* __restrict__ w,
                              float* __restrict__ out) {
    int n = blockIdx.x;
    int d = threadIdx.x;  // 256
    int k = g_idx[n];
    float ze = z[(size_t)n * DD + d];
    float wv = w[(size_t)k * DD + d];
    out[OFF_ZQ + (size_t)n * DD + d] = __fadd_rn(ze, __fsub_rn(wv, ze));
    float diff = __fsub_rn(ze, wv);
    float s = __fmul_rn(diff, diff);
    __shared__ float red[8];
    #pragma unroll
    for (int o = 16; o > 0; o >>= 1) s += __shfl_down_sync(0xffffffffu, s, o);
    if ((threadIdx.x & 31) == 0) red[threadIdx.x >> 5] = s;
    __syncthreads();
    if (threadIdx.x == 0) {
        float t = 0.f;
        #pragma unroll
        for (int i = 0; i < 8; i++) t += red[i];
        g_cpart[n] = t;
        atomicAdd(&g_cnt[k], 1);
    }
    atomicAdd(&out[OFF_AVG + (size_t)k * DD + d], __fmul_rn(ONE_MINUS_DECAY, ze));
}

// ======================= kernel 7: new_count =======================
__global__ void count_kernel(const float* __restrict__ ema_count, float* __restrict__ out) {
    int k = blockIdx.x * blockDim.x + threadIdx.x;
    if (k >= KK) return;
    out[OFF_CNT + k] = __fadd_rn(__fmul_rn(DECAY, ema_count[k]),
                                 __fmul_rn(ONE_MINUS_DECAY, (float)g_cnt[k]));
}

// ======================= kernel 8: reductions =======================
__global__ void finalize_kernel(float* __restrict__ out) {
    __shared__ float sh[1024];
    int t = threadIdx.x;
    float s = 0.f;
    for (int i = t; i < NN; i += 1024) s += g_cpart[i];
    sh[t] = s;
    __syncthreads();
    for (int o = 512; o > 0; o >>= 1) {
        if (t < o) sh[t] += sh[t + o];
        __syncthreads();
    }
    if (t == 0) {
        float mean = __fdiv_rn(sh[0], (float)((size_t)NN * DD));
        out[OFF_COMMIT] = __fmul_rn(BETA, mean);
    }
    __syncthreads();
    float c = 0.f;
    for (int i = t; i < KK; i += 1024) c += out[OFF_CNT + i];
    sh[t] = c;
    __syncthreads();
    for (int o = 512; o > 0; o >>= 1) {
        if (t < o) sh[t] += sh[t + o];
        __syncthreads();
    }
    if (t == 0) g_nsum = sh[0];
}

// ======================= kernel 9: new_embed =======================
__global__ void embed_kernel(float* __restrict__ out) {
    size_t i = (size_t)blockIdx.x * blockDim.x + threadIdx.x;
    if (i >= (size_t)KK * DD) return;
    int k = (int)(i / DD);
    float n = g_nsum;
    float cnt = out[OFF_CNT + k];
    float cs = __fmul_rn(__fdiv_rn(__fadd_rn(cnt, EPS), __fadd_rn(n, K_EPS)), n);
    out[OFF_EMB + i] = __fdiv_rn(out[OFF_AVG + i], cs);
}

// ======================= launch =======================
extern "C" void kernel_launch(void* const* d_in, const int* in_sizes, int n_in,
                              void* d_out, int out_size) {
    const float* z  = (const float*)d_in[0];
    const float* w  = (const float*)d_in[1];
    const float* ec = (const float*)d_in[2];
    const float* ea = (const float*)d_in[3];
    float* out = (float*)d_out;

    cudaFuncSetAttribute(gemm_score_kernel, cudaFuncAttributeMaxDynamicSharedMemorySize,
                         SMEM_TOTAL);

    norms_kernel<<<NN / 256, 256>>>(z, w);
    split_kernel<<<(NN * DD + 255) / 256, 256>>>(z, w);
    init_kernel<<<(KK * DD + 255) / 256, 256>>>(ea, out);
    dim3 grid(NTILES, NN / BM);   // 128 x 256
    gemm_score_kernel<<<grid, 256, SMEM_TOTAL>>>();
    rescore_kernel<<<(NN * 32 + 255) / 256, 256>>>(z, w, out);
    gather_kernel<<<NN, 256>>>(z, w, out);
    count_kernel<<<KK / 256, 256>>>(ec, out);
    finalize_kernel<<<1, 1024>>>(out);
    embed_kernel<<<(KK * DD + 255) / 256, 256>>>(out);
    (void)in_sizes; (void)n_in; (void)out_size;
}

// round 12
// speedup vs baseline: 116.4555x; 1.0677x over previous
#include <cuda_runtime.h>
#include <cuda_bf16.h>
#include <math_constants.h>
#include <cstdint>

// Problem constants
#define NN 32768
#define KK 8192
#define DD 256
#define BETA 0.25f
#define DECAY 0.99f
#define ONE_MINUS_DECAY 0.01f
#define EPS 1e-5f
#define K_EPS 0.08192f

// Output layout (float32): z_q_st, commitment, idx, new_embed, new_count, new_avg
#define OFF_ZQ     0
#define OFF_COMMIT ((size_t)NN * DD)
#define OFF_IDX    (OFF_COMMIT + 1)
#define OFF_EMB    (OFF_IDX + NN)
#define OFF_CNT    (OFF_EMB + (size_t)KK * DD)
#define OFF_AVG    (OFF_CNT + KK)

// GEMM tiling (baseline mma.sync path — compute_103-safe)
#define BM 128
#define BN 64
#define KC 128             // K chunk (elements) staged in smem per step
#define NKC (DD / KC)      // 2
#define NTILES (KK / BN)   // 128
#define MARGIN 6e-4f
#define CAP 8

// Scratch (device globals — no allocations allowed)
__device__ float g_wnorm[KK];
__device__ float g_znorm[NN];
__device__ int   g_idx[NN];
__device__ int   g_cnt[KK];
__device__ float g_cpart[NN];
__device__ float g_nsum;
__device__ __nv_bfloat16 g_zh[(size_t)NN * DD];
__device__ __nv_bfloat16 g_wh[(size_t)KK * DD];
__device__ float         g_tilemin[(size_t)NN * NTILES];
__device__ int           g_cand[(size_t)NN * NTILES * CAP];
__device__ unsigned char g_ccnt[(size_t)NN * NTILES];   // RAW count (saturated 255)

// ======================= baseline PTX helpers =======================
__device__ __forceinline__ uint32_t smem_u32(const void* p) {
    uint32_t a;
    asm("{ .reg .u64 t; cvta.to.shared.u64 t, %1; cvt.u32.u64 %0, t; }" : "=r"(a) : "l"(p));
    return a;
}
#define CP_ASYNC16(dst, src) \
    asm volatile("cp.async.cg.shared.global [%0], [%1], 16;" :: "r"(dst), "l"(src) : "memory")
#define CP_COMMIT() asm volatile("cp.async.commit_group;" ::: "memory")
#define CP_WAIT0()  asm volatile("cp.async.wait_group 0;" ::: "memory")
#define LDSM4(r0, r1, r2, r3, addr) \
    asm volatile("ldmatrix.sync.aligned.m8n8.x4.shared.b16 {%0,%1,%2,%3}, [%4];" \
        : "=r"(r0), "=r"(r1), "=r"(r2), "=r"(r3) : "r"(addr))
#define MMA16816(d, a0, a1, a2, a3, b0, b1) \
    asm volatile("mma.sync.aligned.m16n8k16.row.col.f32.bf16.bf16.f32 " \
        "{%0,%1,%2,%3}, {%4,%5,%6,%7}, {%8,%9}, {%0,%1,%2,%3};" \
        : "+f"((d)[0]), "+f"((d)[1]), "+f"((d)[2]), "+f"((d)[3]) \
        : "r"(a0), "r"(a1), "r"(a2), "r"(a3), "r"(b0), "r"(b1))

// Swizzled smem byte offset for (row, k-element) in a [rows][128 bf16] chunk tile.
// Row stride 256B; 16B chunks XOR-permuted within each 128B group by row&7.
__device__ __forceinline__ uint32_t sw_off(int row, int kelem) {
    int kc = kelem >> 3;               // 16B chunk index within row (0..15)
    return (uint32_t)(row * 256 + ((kc >> 3) << 7) + (((kc & 7) ^ (row & 7)) << 4));
}

// ======================= kernel 1: exact row norms =======================
__global__ void norms_kernel(const float* __restrict__ z, const float* __restrict__ w) {
    int r = blockIdx.x * blockDim.x + threadIdx.x;
    if (r < NN) {
        const float* p = z + (size_t)r * DD;
        float s = 0.f;
        for (int i = 0; i < DD; ++i) s = __fadd_rn(s, __fmul_rn(p[i], p[i]));
        g_znorm[r] = s;
    }
    if (r < KK) {
        const float* p = w + (size_t)r * DD;
        float s = 0.f;
        for (int i = 0; i < DD; ++i) s = __fadd_rn(s, __fmul_rn(p[i], p[i]));
        g_wnorm[r] = s;
    }
}

// ======================= kernel 2: bf16 hi conversion =======================
__global__ void split_kernel(const float* __restrict__ z, const float* __restrict__ w) {
    size_t i = (size_t)blockIdx.x * blockDim.x + threadIdx.x;
    if (i < (size_t)NN * DD) g_zh[i] = __float2bfloat16(z[i]);
    if (i < (size_t)KK * DD) g_wh[i] = __float2bfloat16(w[i]);
}

// ======================= kernel 3: init =======================
__global__ void init_kernel(const float* __restrict__ ema_avg, float* __restrict__ out) {
    size_t i = (size_t)blockIdx.x * blockDim.x + threadIdx.x;
    if (i < (size_t)KK * DD) out[OFF_AVG + i] = __fmul_rn(DECAY, ema_avg[i]);
    if (i < KK) g_cnt[i] = 0;
}

// ======================= kernel 4: mma.sync GEMM + candidate collection ==========
// K staged in 2 chunks of 128 to halve smem -> 3 CTAs/SM.
// SMEM: As [128][128] bf16 swizzled (32KB) | Bs [64][128] bf16 (16KB) |
//       rowmin[2][128] f32 | rowcnt[128] i32
#define SM_A 0
#define SM_B (BM * 256)                      // 32768
#define SM_RMIN (SM_B + BN * 256)            // 49152
#define SM_RCNT (SM_RMIN + 2 * BM * 4)       // 50176
#define SMEM_TOTAL (SM_RCNT + BM * 4)        // 50688

__global__ void __launch_bounds__(256, 3)
gemm_score_kernel() {
    extern __shared__ char smem[];
    uint32_t sb = smem_u32(smem);
    const int tid = threadIdx.x;
    const int lane = tid & 31, wid = tid >> 5;
    const int warpm = wid >> 1, warpn = wid & 1;
    const int ntile = blockIdx.x;
    const int mtile = blockIdx.y;
    const int mb = warpm * 32;
    const int nb = warpn * 32;

    float* rm = reinterpret_cast<float*>(smem + SM_RMIN);
    int*   rc = reinterpret_cast<int*>(smem + SM_RCNT);
    if (tid < 2 * BM) rm[tid] = CUDART_INF_F;
    if (tid < BM) rc[tid] = 0;

    const __nv_bfloat16* gA = g_zh + (size_t)(mtile * BM) * DD;
    const __nv_bfloat16* gB = g_wh + (size_t)(ntile * BN) * DD;

    float acc[2][4][4];
    #pragma unroll
    for (int ms = 0; ms < 2; ++ms)
        #pragma unroll
        for (int ns = 0; ns < 4; ++ns)
            #pragma unroll
            for (int j = 0; j < 4; ++j) acc[ms][ns][j] = 0.f;

    const int arow = mb + (lane & 7) + ((lane >> 3) & 1) * 8;
    const int brow = nb + (lane & 7) + (lane >> 4) * 8;

    #pragma unroll
    for (int c = 0; c < NKC; ++c) {
        if (c > 0) __syncthreads();   // all warps done reading previous chunk
        // stage A chunk [128][128] (32KB): 2048 16B-chunks / 256 thr = 8 iters
        #pragma unroll
        for (int i = 0; i < 8; ++i) {
            int lin = tid + i * 256;
            int r = lin >> 4, kc = lin & 15;
            CP_ASYNC16(sb + SM_A + r * 256 + ((kc >> 3) << 7) + (((kc & 7) ^ (r & 7)) << 4),
                       gA + (size_t)r * DD + c * KC + kc * 8);
        }
        // stage B chunk [64][128] (16KB): 1024 chunks / 256 thr = 4 iters
        #pragma unroll
        for (int i = 0; i < 4; ++i) {
            int lin = tid + i * 256;
            int r = lin >> 4, kc = lin & 15;
            CP_ASYNC16(sb + SM_B + r * 256 + ((kc >> 3) << 7) + (((kc & 7) ^ (r & 7)) << 4),
                       gB + (size_t)r * DD + c * KC + kc * 8);
        }
        CP_COMMIT();
        CP_WAIT0();
        __syncthreads();

        // 8 k-steps of m32 x n32 x k16 per warp
        #pragma unroll
        for (int ks = 0; ks < 8; ++ks) {
            const int ak = ks * 16 + (lane >> 4) * 8;
            const int bk = ks * 16 + ((lane >> 3) & 1) * 8;
            uint32_t a0, a1, a2, a3, a4, a5, a6, a7;
            uint32_t b0, b1, b2, b3, b4, b5, b6, b7;
            LDSM4(a0, a1, a2, a3, sb + SM_A + sw_off(arow, ak));
            LDSM4(a4, a5, a6, a7, sb + SM_A + sw_off(arow + 16, ak));
            LDSM4(b0, b1, b2, b3, sb + SM_B + sw_off(brow, bk));
            LDSM4(b4, b5, b6, b7, sb + SM_B + sw_off(brow + 16, bk));
            MMA16816(acc[0][0], a0, a1, a2, a3, b0, b1);
            MMA16816(acc[0][1], a0, a1, a2, a3, b2, b3);
            MMA16816(acc[0][2], a0, a1, a2, a3, b4, b5);
            MMA16816(acc[0][3], a0, a1, a2, a3, b6, b7);
            MMA16816(acc[1][0], a4, a5, a6, a7, b0, b1);
            MMA16816(acc[1][1], a4, a5, a6, a7, b2, b3);
            MMA16816(acc[1][2], a4, a5, a6, a7, b4, b5);
            MMA16816(acc[1][3], a4, a5, a6, a7, b6, b7);
        }
    }

    // pass 1: per-row minima of approx scores s = wn - 2*dot
    const float* wn = g_wnorm + ntile * BN;
    float wnv[4][2];
    #pragma unroll
    for (int ns = 0; ns < 4; ++ns) {
        int c0 = nb + ns * 8 + (lane & 3) * 2;
        wnv[ns][0] = wn[c0];
        wnv[ns][1] = wn[c0 + 1];
    }
    float rmn[2][2] = {{CUDART_INF_F, CUDART_INF_F}, {CUDART_INF_F, CUDART_INF_F}};
    #pragma unroll
    for (int ms = 0; ms < 2; ++ms)
        #pragma unroll
        for (int ns = 0; ns < 4; ++ns) {
            float s0 = fmaf(-2.f, acc[ms][ns][0], wnv[ns][0]);
            float s1 = fmaf(-2.f, acc[ms][ns][1], wnv[ns][1]);
            float s2 = fmaf(-2.f, acc[ms][ns][2], wnv[ns][0]);
            float s3 = fmaf(-2.f, acc[ms][ns][3], wnv[ns][1]);
            rmn[ms][0] = fminf(rmn[ms][0], fminf(s0, s1));
            rmn[ms][1] = fminf(rmn[ms][1], fminf(s2, s3));
        }
    #pragma unroll
    for (int ms = 0; ms < 2; ++ms)
        #pragma unroll
        for (int h = 0; h < 2; ++h) {
            float v = rmn[ms][h];
            v = fminf(v, __shfl_xor_sync(0xffffffffu, v, 1));
            v = fminf(v, __shfl_xor_sync(0xffffffffu, v, 2));
            if ((lane & 3) == 0)
                rm[warpn * BM + mb + ms * 16 + h * 8 + (lane >> 2)] = v;
        }
    __syncthreads();

    // pass 2: collect candidates within MARGIN of row min (count raw)
    #pragma unroll
    for (int ms = 0; ms < 2; ++ms)
        #pragma unroll
        for (int ns = 0; ns < 4; ++ns)
            #pragma unroll
            for (int j = 0; j < 4; ++j) {
                int lr = mb + ms * 16 + ((j >> 1) << 3) + (lane >> 2);
                float thr = fminf(rm[lr], rm[BM + lr]) + MARGIN;
                float sv = fmaf(-2.f, acc[ms][ns][j], wnv[ns][j & 1]);
                if (sv <= thr) {
                    int pos = atomicAdd(&rc[lr], 1);
                    if (pos < CAP) {
                        int col = ntile * BN + nb + ns * 8 + (lane & 3) * 2 + (j & 1);
                        g_cand[((size_t)(mtile * BM + lr) * NTILES + ntile) * CAP + pos] = col;
                    }
                }
            }
    __syncthreads();

    if (tid < BM) {
        int row = mtile * BM + tid;
        int c = rc[tid];
        g_ccnt[(size_t)row * NTILES + ntile] = (unsigned char)(c > 255 ? 255 : c);
        g_tilemin[(size_t)row * NTILES + ntile] = fminf(rm[tid], rm[BM + tid]);
    }
}

// ======================= kernel 5: exact rescore + argmin =======================
__device__ __forceinline__ float exact_dist(const float* __restrict__ zr,
                                            const float* __restrict__ w,
                                            float zn, int k) {
    const float* wr = w + (size_t)k * DD;
    float dot = 0.f;
    #pragma unroll 8
    for (int i = 0; i < DD; ++i) dot = __fmaf_rn(zr[i], wr[i], dot);
    return __fadd_rn(__fsub_rn(zn, 2.0f * dot), g_wnorm[k]);
}

__global__ void rescore_kernel(const float* __restrict__ z, const float* __restrict__ w,
                               float* __restrict__ out) {
    int gw = (blockIdx.x * blockDim.x + threadIdx.x) >> 5;
    int lane = threadIdx.x & 31;
    if (gw >= NN) return;
    int n = gw;
    float tmv[4];
    #pragma unroll
    for (int j = 0; j < 4; ++j)
        tmv[j] = g_tilemin[(size_t)n * NTILES + lane + 32 * j];
    float gmin = fminf(fminf(tmv[0], tmv[1]), fminf(tmv[2], tmv[3]));
    #pragma unroll
    for (int o = 16; o > 0; o >>= 1) gmin = fminf(gmin, __shfl_xor_sync(0xffffffffu, gmin, o));
    float zn = g_znorm[n];
    const float* zr = z + (size_t)n * DD;
    float bv = CUDART_INF_F;
    int bi = 0x7fffffff;
    float thr = gmin + MARGIN;
    #pragma unroll
    for (int j = 0; j < 4; ++j) {
        if (tmv[j] <= thr) {
            int t = lane + 32 * j;
            int c = g_ccnt[(size_t)n * NTILES + t];
            if (c <= CAP) {
                size_t cbase = ((size_t)n * NTILES + t) * CAP;
                for (int q = 0; q < c; ++q) {
                    int k = g_cand[cbase + q];
                    float d = exact_dist(zr, w, zn, k);
                    if (d < bv || (d == bv && k < bi)) { bv = d; bi = k; }
                }
            } else {
                // overflowed tile: exact rescan of its 64 columns (bounded)
                int k0 = t * BN;
                for (int k = k0; k < k0 + BN; ++k) {
                    float d = exact_dist(zr, w, zn, k);
                    if (d < bv || (d == bv && k < bi)) { bv = d; bi = k; }
                }
            }
        }
    }
    #pragma unroll
    for (int o = 16; o > 0; o >>= 1) {
        float ov = __shfl_down_sync(0xffffffffu, bv, o);
        int   oi = __shfl_down_sync(0xffffffffu, bi, o);
        if (ov < bv || (ov == bv && oi < bi)) { bv = ov; bi = oi; }
    }
    if (lane == 0) {
        g_idx[n] = bi;
        out[OFF_IDX + n] = (float)bi;
    }
}

// ======================= kernel 6: gather + commitment + EMA scatter ===========
__global__ void gather_kernel(const float* __restrict__ z, const float* __restrict__ w,
                              float* __restrict__ out) {
    int n = blockIdx.x;
    int d = threadIdx.x;  // 256
    int k = g_idx[n];
    float ze = z[(size_t)n * DD + d];
    float wv = w[(size_t)k * DD + d];
    out[OFF_ZQ + (size_t)n * DD + d] = __fadd_rn(ze, __fsub_rn(wv, ze));
    float diff = __fsub_rn(ze, wv);
    float s = __fmul_rn(diff, diff);
    __shared__ float red[8];
    #pragma unroll
    for (int o = 16; o > 0; o >>= 1) s += __shfl_down_sync(0xffffffffu, s, o);
    if ((threadIdx.x & 31) == 0) red[threadIdx.x >> 5] = s;
    __syncthreads();
    if (threadIdx.x == 0) {
        float t = 0.f;
        #pragma unroll
        for (int i = 0; i < 8; i++) t += red[i];
        g_cpart[n] = t;
        atomicAdd(&g_cnt[k], 1);
    }
    atomicAdd(&out[OFF_AVG + (size_t)k * DD + d], __fmul_rn(ONE_MINUS_DECAY, ze));
}

// ======================= kernel 7: new_count =======================
__global__ void count_kernel(const float* __restrict__ ema_count, float* __restrict__ out) {
    int k = blockIdx.x * blockDim.x + threadIdx.x;
    if (k >= KK) return;
    out[OFF_CNT + k] = __fadd_rn(__fmul_rn(DECAY, ema_count[k]),
                                 __fmul_rn(ONE_MINUS_DECAY, (float)g_cnt[k]));
}

// ======================= kernel 8: reductions =======================
__global__ void finalize_kernel(float* __restrict__ out) {
    __shared__ float sh[1024];
    int t = threadIdx.x;
    float s = 0.f;
    for (int i = t; i < NN; i += 1024) s += g_cpart[i];
    sh[t] = s;
    __syncthreads();
    for (int o = 512; o > 0; o >>= 1) {
        if (t < o) sh[t] += sh[t + o];
        __syncthreads();
    }
    if (t == 0) {
        float mean = __fdiv_rn(sh[0], (float)((size_t)NN * DD));
        out[OFF_COMMIT] = __fmul_rn(BETA, mean);
    }
    __syncthreads();
    float c = 0.f;
    for (int i = t; i < KK; i += 1024) c += out[OFF_CNT + i];
    sh[t] = c;
    __syncthreads();
    for (int o = 512; o > 0; o >>= 1) {
        if (t < o) sh[t] += sh[t + o];
        __syncthreads();
    }
    if (t == 0) g_nsum = sh[0];
}

// ======================= kernel 9: new_embed =======================
__global__ void embed_kernel(float* __restrict__ out) {
    size_t i = (size_t)blockIdx.x * blockDim.x + threadIdx.x;
    if (i >= (size_t)KK * DD) return;
    int k = (int)(i / DD);
    float n = g_nsum;
    float cnt = out[OFF_CNT + k];
    float cs = __fmul_rn(__fdiv_rn(__fadd_rn(cnt, EPS), __fadd_rn(n, K_EPS)), n);
    out[OFF_EMB + i] = __fdiv_rn(out[OFF_AVG + i], cs);
}

// ======================= launch =======================
extern "C" void kernel_launch(void* const* d_in, const int* in_sizes, int n_in,
                              void* d_out, int out_size) {
    const float* z  = (const float*)d_in[0];
    const float* w  = (const float*)d_in[1];
    const float* ec = (const float*)d_in[2];
    const float* ea = (const float*)d_in[3];
    float* out = (float*)d_out;

    cudaFuncSetAttribute(gemm_score_kernel, cudaFuncAttributeMaxDynamicSharedMemorySize,
                         SMEM_TOTAL);

    norms_kernel<<<NN / 256, 256>>>(z, w);
    split_kernel<<<(NN * DD + 255) / 256, 256>>>(z, w);
    init_kernel<<<(KK * DD + 255) / 256, 256>>>(ea, out);
    dim3 grid(NTILES, NN / BM);   // 128 x 256
    gemm_score_kernel<<<grid, 256, SMEM_TOTAL>>>();
    rescore_kernel<<<(NN * 32 + 255) / 256, 256>>>(z, w, out);
    gather_kernel<<<NN, 256>>>(z, w, out);
    count_kernel<<<KK / 256, 256>>>(ec, out);
    finalize_kernel<<<1, 1024>>>(out);
    embed_kernel<<<(KK * DD + 255) / 256, 256>>>(out);
    (void)in_sizes; (void)n_in; (void)out_size;
}

// round 16
// speedup vs baseline: 138.6140x; 1.1903x over previous
#include <cuda_runtime.h>
#include <cuda_bf16.h>
#include <math_constants.h>
#include <cstdint>

// Problem constants
#define NN 32768
#define KK 8192
#define DD 256
#define BETA 0.25f
#define DECAY 0.99f
#define ONE_MINUS_DECAY 0.01f
#define EPS 1e-5f
#define K_EPS 0.08192f

// Output layout (float32): z_q_st, commitment, idx, new_embed, new_count, new_avg
#define OFF_ZQ     0
#define OFF_COMMIT ((size_t)NN * DD)
#define OFF_IDX    (OFF_COMMIT + 1)
#define OFF_EMB    (OFF_IDX + NN)
#define OFF_CNT    (OFF_EMB + (size_t)KK * DD)
#define OFF_AVG    (OFF_CNT + KK)

// GEMM tiling (baseline mma.sync path — compute_103-safe)
#define BM 128
#define BN 128             // CTA N tile (widened; warp tile 32x64)
#define KC 128             // K chunk (elements) staged in smem per step
#define NKC (DD / KC)      // 2
#define NTILES (KK / BN)   // 64
#define MARGIN 6e-4f
#define CAP 8

// Scratch (device globals — no allocations allowed)
__device__ float g_wnorm[KK];
__device__ float g_znorm[NN];
__device__ int   g_idx[NN];
__device__ int   g_cnt[KK];
__device__ float g_cpart[NN];
__device__ float g_nsum;
__device__ __nv_bfloat16 g_zh[(size_t)NN * DD];
__device__ __nv_bfloat16 g_wh[(size_t)KK * DD];
__device__ float         g_tilemin[(size_t)NN * NTILES];
__device__ int           g_cand[(size_t)NN * NTILES * CAP];
__device__ unsigned char g_ccnt[(size_t)NN * NTILES];   // RAW count (saturated 255)

// ======================= baseline PTX helpers =======================
__device__ __forceinline__ uint32_t smem_u32(const void* p) {
    uint32_t a;
    asm("{ .reg .u64 t; cvta.to.shared.u64 t, %1; cvt.u32.u64 %0, t; }" : "=r"(a) : "l"(p));
    return a;
}
#define CP_ASYNC16(dst, src) \
    asm volatile("cp.async.cg.shared.global [%0], [%1], 16;" :: "r"(dst), "l"(src) : "memory")
#define CP_COMMIT() asm volatile("cp.async.commit_group;" ::: "memory")
#define CP_WAIT0()  asm volatile("cp.async.wait_group 0;" ::: "memory")
#define LDSM4(r0, r1, r2, r3, addr) \
    asm volatile("ldmatrix.sync.aligned.m8n8.x4.shared.b16 {%0,%1,%2,%3}, [%4];" \
        : "=r"(r0), "=r"(r1), "=r"(r2), "=r"(r3) : "r"(addr))
#define MMA16816(d, a0, a1, a2, a3, b0, b1) \
    asm volatile("mma.sync.aligned.m16n8k16.row.col.f32.bf16.bf16.f32 " \
        "{%0,%1,%2,%3}, {%4,%5,%6,%7}, {%8,%9}, {%0,%1,%2,%3};" \
        : "+f"((d)[0]), "+f"((d)[1]), "+f"((d)[2]), "+f"((d)[3]) \
        : "r"(a0), "r"(a1), "r"(a2), "r"(a3), "r"(b0), "r"(b1))

// Swizzled smem byte offset for (row, k-element) in a [rows][128 bf16] chunk tile.
__device__ __forceinline__ uint32_t sw_off(int row, int kelem) {
    int kc = kelem >> 3;               // 16B chunk index within row (0..15)
    return (uint32_t)(row * 256 + ((kc >> 3) << 7) + (((kc & 7) ^ (row & 7)) << 4));
}

// ======================= kernel 1: exact row norms =======================
__global__ void norms_kernel(const float* __restrict__ z, const float* __restrict__ w) {
    int r = blockIdx.x * blockDim.x + threadIdx.x;
    if (r < NN) {
        const float* p = z + (size_t)r * DD;
        float s = 0.f;
        for (int i = 0; i < DD; ++i) s = __fadd_rn(s, __fmul_rn(p[i], p[i]));
        g_znorm[r] = s;
    }
    if (r < KK) {
        const float* p = w + (size_t)r * DD;
        float s = 0.f;
        for (int i = 0; i < DD; ++i) s = __fadd_rn(s, __fmul_rn(p[i], p[i]));
        g_wnorm[r] = s;
    }
}

// ======================= kernel 2: bf16 hi conversion =======================
__global__ void split_kernel(const float* __restrict__ z, const float* __restrict__ w) {
    size_t i = (size_t)blockIdx.x * blockDim.x + threadIdx.x;
    if (i < (size_t)NN * DD) g_zh[i] = __float2bfloat16(z[i]);
    if (i < (size_t)KK * DD) g_wh[i] = __float2bfloat16(w[i]);
}

// ======================= kernel 3: init =======================
__global__ void init_kernel(const float* __restrict__ ema_avg, float* __restrict__ out) {
    size_t i = (size_t)blockIdx.x * blockDim.x + threadIdx.x;
    if (i < (size_t)KK * DD) out[OFF_AVG + i] = __fmul_rn(DECAY, ema_avg[i]);
    if (i < KK) g_cnt[i] = 0;
}

// ======================= kernel 4: mma.sync GEMM + candidate collection ==========
// CTA tile 128x128, warp tile 32x64 (warps 4x2). K in 2 chunks of 128.
// SMEM: As [128][128] 32KB | Bs [128][128] 32KB | rowmin[2][128] | rowcnt[128]
#define SM_A 0
#define SM_B (BM * 256)                      // 32768
#define SM_RMIN (SM_B + BN * 256)            // 65536
#define SM_RCNT (SM_RMIN + 2 * BM * 4)       // 66560
#define SMEM_TOTAL (SM_RCNT + BM * 4)        // 67072

__global__ void __launch_bounds__(256, 2)
gemm_score_kernel() {
    extern __shared__ char smem[];
    uint32_t sb = smem_u32(smem);
    const int tid = threadIdx.x;
    const int lane = tid & 31, wid = tid >> 5;
    const int warpm = wid >> 1, warpn = wid & 1;
    const int ntile = blockIdx.x;    // 0..63
    const int mtile = blockIdx.y;    // 0..255
    const int mb = warpm * 32;       // warp row base
    const int nb = warpn * 64;       // warp col base (64-wide warp tile)

    float* rm = reinterpret_cast<float*>(smem + SM_RMIN);
    int*   rc = reinterpret_cast<int*>(smem + SM_RCNT);
    if (tid < 2 * BM) rm[tid] = CUDART_INF_F;
    if (tid < BM) rc[tid] = 0;

    const __nv_bfloat16* gA = g_zh + (size_t)(mtile * BM) * DD;
    const __nv_bfloat16* gB = g_wh + (size_t)(ntile * BN) * DD;

    float acc[2][8][4];
    #pragma unroll
    for (int ms = 0; ms < 2; ++ms)
        #pragma unroll
        for (int ns = 0; ns < 8; ++ns)
            #pragma unroll
            for (int j = 0; j < 4; ++j) acc[ms][ns][j] = 0.f;

    const int arow = mb + (lane & 7) + ((lane >> 3) & 1) * 8;
    const int brow = nb + (lane & 7) + (lane >> 4) * 8;

    #pragma unroll
    for (int c = 0; c < NKC; ++c) {
        if (c > 0) __syncthreads();
        // stage A chunk [128][128] (32KB): 2048 16B-chunks / 256 thr = 8 iters
        #pragma unroll
        for (int i = 0; i < 8; ++i) {
            int lin = tid + i * 256;
            int r = lin >> 4, kc = lin & 15;
            CP_ASYNC16(sb + SM_A + r * 256 + ((kc >> 3) << 7) + (((kc & 7) ^ (r & 7)) << 4),
                       gA + (size_t)r * DD + c * KC + kc * 8);
        }
        // stage B chunk [128][128] (32KB): 2048 chunks / 256 thr = 8 iters
        #pragma unroll
        for (int i = 0; i < 8; ++i) {
            int lin = tid + i * 256;
            int r = lin >> 4, kc = lin & 15;
            CP_ASYNC16(sb + SM_B + r * 256 + ((kc >> 3) << 7) + (((kc & 7) ^ (r & 7)) << 4),
                       gB + (size_t)r * DD + c * KC + kc * 8);
        }
        CP_COMMIT();
        CP_WAIT0();
        __syncthreads();

        // 8 k-steps of m32 x n64 x k16 per warp
        #pragma unroll
        for (int ks = 0; ks < 8; ++ks) {
            const int ak = ks * 16 + (lane >> 4) * 8;
            const int bk = ks * 16 + ((lane >> 3) & 1) * 8;
            uint32_t a0, a1, a2, a3, a4, a5, a6, a7;
            uint32_t bfr[16];
            LDSM4(a0, a1, a2, a3, sb + SM_A + sw_off(arow, ak));
            LDSM4(a4, a5, a6, a7, sb + SM_A + sw_off(arow + 16, ak));
            LDSM4(bfr[0], bfr[1], bfr[2], bfr[3],   sb + SM_B + sw_off(brow,      bk));
            LDSM4(bfr[4], bfr[5], bfr[6], bfr[7],   sb + SM_B + sw_off(brow + 16, bk));
            LDSM4(bfr[8], bfr[9], bfr[10], bfr[11], sb + SM_B + sw_off(brow + 32, bk));
            LDSM4(bfr[12], bfr[13], bfr[14], bfr[15], sb + SM_B + sw_off(brow + 48, bk));
            #pragma unroll
            for (int ns = 0; ns < 8; ++ns) {
                MMA16816(acc[0][ns], a0, a1, a2, a3, bfr[ns * 2], bfr[ns * 2 + 1]);
                MMA16816(acc[1][ns], a4, a5, a6, a7, bfr[ns * 2], bfr[ns * 2 + 1]);
            }
        }
    }

    // pass 1: per-row minima of approx scores s = wn - 2*dot
    const float* wn = g_wnorm + ntile * BN;
    float wnv[8][2];
    #pragma unroll
    for (int ns = 0; ns < 8; ++ns) {
        int c0 = nb + ns * 8 + (lane & 3) * 2;
        wnv[ns][0] = wn[c0];
        wnv[ns][1] = wn[c0 + 1];
    }
    float rmn[2][2] = {{CUDART_INF_F, CUDART_INF_F}, {CUDART_INF_F, CUDART_INF_F}};
    #pragma unroll
    for (int ms = 0; ms < 2; ++ms)
        #pragma unroll
        for (int ns = 0; ns < 8; ++ns) {
            float s0 = fmaf(-2.f, acc[ms][ns][0], wnv[ns][0]);
            float s1 = fmaf(-2.f, acc[ms][ns][1], wnv[ns][1]);
            float s2 = fmaf(-2.f, acc[ms][ns][2], wnv[ns][0]);
            float s3 = fmaf(-2.f, acc[ms][ns][3], wnv[ns][1]);
            rmn[ms][0] = fminf(rmn[ms][0], fminf(s0, s1));
            rmn[ms][1] = fminf(rmn[ms][1], fminf(s2, s3));
        }
    #pragma unroll
    for (int ms = 0; ms < 2; ++ms)
        #pragma unroll
        for (int h = 0; h < 2; ++h) {
            float v = rmn[ms][h];
            v = fminf(v, __shfl_xor_sync(0xffffffffu, v, 1));
            v = fminf(v, __shfl_xor_sync(0xffffffffu, v, 2));
            if ((lane & 3) == 0)
                rm[warpn * BM + mb + ms * 16 + h * 8 + (lane >> 2)] = v;
        }
    __syncthreads();

    // pass 2: collect candidates within MARGIN of row min (count raw)
    #pragma unroll
    for (int ms = 0; ms < 2; ++ms)
        #pragma unroll
        for (int ns = 0; ns < 8; ++ns)
            #pragma unroll
            for (int j = 0; j < 4; ++j) {
                int lr = mb + ms * 16 + ((j >> 1) << 3) + (lane >> 2);
                float thr = fminf(rm[lr], rm[BM + lr]) + MARGIN;
                float sv = fmaf(-2.f, acc[ms][ns][j], wnv[ns][j & 1]);
                if (sv <= thr) {
                    int pos = atomicAdd(&rc[lr], 1);
                    if (pos < CAP) {
                        int col = ntile * BN + nb + ns * 8 + (lane & 3) * 2 + (j & 1);
                        g_cand[((size_t)(mtile * BM + lr) * NTILES + ntile) * CAP + pos] = col;
                    }
                }
            }
    __syncthreads();

    if (tid < BM) {
        int row = mtile * BM + tid;
        int c = rc[tid];
        g_ccnt[(size_t)row * NTILES + ntile] = (unsigned char)(c > 255 ? 255 : c);
        g_tilemin[(size_t)row * NTILES + ntile] = fminf(rm[tid], rm[BM + tid]);
    }
}

// ======================= kernel 5: exact rescore + argmin =======================
__device__ __forceinline__ float exact_dist(const float* __restrict__ zr,
                                            const float* __restrict__ w,
                                            float zn, int k) {
    const float* wr = w + (size_t)k * DD;
    float dot = 0.f;
    #pragma unroll 8
    for (int i = 0; i < DD; ++i) dot = __fmaf_rn(zr[i], wr[i], dot);
    return __fadd_rn(__fsub_rn(zn, 2.0f * dot), g_wnorm[k]);
}

__global__ void rescore_kernel(const float* __restrict__ z, const float* __restrict__ w,
                               float* __restrict__ out) {
    int gw = (blockIdx.x * blockDim.x + threadIdx.x) >> 5;
    int lane = threadIdx.x & 31;
    if (gw >= NN) return;
    int n = gw;
    float tmv[2];
    #pragma unroll
    for (int j = 0; j < 2; ++j)
        tmv[j] = g_tilemin[(size_t)n * NTILES + lane + 32 * j];
    float gmin = fminf(tmv[0], tmv[1]);
    #pragma unroll
    for (int o = 16; o > 0; o >>= 1) gmin = fminf(gmin, __shfl_xor_sync(0xffffffffu, gmin, o));
    float zn = g_znorm[n];
    const float* zr = z + (size_t)n * DD;
    float bv = CUDART_INF_F;
    int bi = 0x7fffffff;
    float thr = gmin + MARGIN;
    #pragma unroll
    for (int j = 0; j < 2; ++j) {
        if (tmv[j] <= thr) {
            int t = lane + 32 * j;
            int c = g_ccnt[(size_t)n * NTILES + t];
            if (c <= CAP) {
                size_t cbase = ((size_t)n * NTILES + t) * CAP;
                for (int q = 0; q < c; ++q) {
                    int k = g_cand[cbase + q];
                    float d = exact_dist(zr, w, zn, k);
                    if (d < bv || (d == bv && k < bi)) { bv = d; bi = k; }
                }
            } else {
                // overflowed tile: exact rescan of its 128 columns (bounded)
                int k0 = t * BN;
                for (int k = k0; k < k0 + BN; ++k) {
                    float d = exact_dist(zr, w, zn, k);
                    if (d < bv || (d == bv && k < bi)) { bv = d; bi = k; }
                }
            }
        }
    }
    #pragma unroll
    for (int o = 16; o > 0; o >>= 1) {
        float ov = __shfl_down_sync(0xffffffffu, bv, o);
        int   oi = __shfl_down_sync(0xffffffffu, bi, o);
        if (ov < bv || (ov == bv && oi < bi)) { bv = ov; bi = oi; }
    }
    if (lane == 0) {
        g_idx[n] = bi;
        out[OFF_IDX + n] = (float)bi;
    }
}

// ======================= kernel 6: gather + commitment + EMA scatter ===========
__global__ void gather_kernel(const float* __restrict__ z, const float* __restrict__ w,
                              float* __restrict__ out) {
    int n = blockIdx.x;
    int d = threadIdx.x;  // 256
    int k = g_idx[n];
    float ze = z[(size_t)n * DD + d];
    float wv = w[(size_t)k * DD + d];
    out[OFF_ZQ + (size_t)n * DD + d] = __fadd_rn(ze, __fsub_rn(wv, ze));
    float diff = __fsub_rn(ze, wv);
    float s = __fmul_rn(diff, diff);
    __shared__ float red[8];
    #pragma unroll
    for (int o = 16; o > 0; o >>= 1) s += __shfl_down_sync(0xffffffffu, s, o);
    if ((threadIdx.x & 31) == 0) red[threadIdx.x >> 5] = s;
    __syncthreads();
    if (threadIdx.x == 0) {
        float t = 0.f;
        #pragma unroll
        for (int i = 0; i < 8; i++) t += red[i];
        g_cpart[n] = t;
        atomicAdd(&g_cnt[k], 1);
    }
    atomicAdd(&out[OFF_AVG + (size_t)k * DD + d], __fmul_rn(ONE_MINUS_DECAY, ze));
}

// ======================= kernel 7: new_count =======================
__global__ void count_kernel(const float* __restrict__ ema_count, float* __restrict__ out) {
    int k = blockIdx.x * blockDim.x + threadIdx.x;
    if (k >= KK) return;
    out[OFF_CNT + k] = __fadd_rn(__fmul_rn(DECAY, ema_count[k]),
                                 __fmul_rn(ONE_MINUS_DECAY, (float)g_cnt[k]));
}

// ======================= kernel 8: reductions =======================
__global__ void finalize_kernel(float* __restrict__ out) {
    __shared__ float sh[1024];
    int t = threadIdx.x;
    float s = 0.f;
    for (int i = t; i < NN; i += 1024) s += g_cpart[i];
    sh[t] = s;
    __syncthreads();
    for (int o = 512; o > 0; o >>= 1) {
        if (t < o) sh[t] += sh[t + o];
        __syncthreads();
    }
    if (t == 0) {
        float mean = __fdiv_rn(sh[0], (float)((size_t)NN * DD));
        out[OFF_COMMIT] = __fmul_rn(BETA, mean);
    }
    __syncthreads();
    float c = 0.f;
    for (int i = t; i < KK; i += 1024) c += out[OFF_CNT + i];
    sh[t] = c;
    __syncthreads();
    for (int o = 512; o > 0; o >>= 1) {
        if (t < o) sh[t] += sh[t + o];
        __syncthreads();
    }
    if (t == 0) g_nsum = sh[0];
}

// ======================= kernel 9: new_embed =======================
__global__ void embed_kernel(float* __restrict__ out) {
    size_t i = (size_t)blockIdx.x * blockDim.x + threadIdx.x;
    if (i >= (size_t)KK * DD) return;
    int k = (int)(i / DD);
    float n = g_nsum;
    float cnt = out[OFF_CNT + k];
    float cs = __fmul_rn(__fdiv_rn(__fadd_rn(cnt, EPS), __fadd_rn(n, K_EPS)), n);
    out[OFF_EMB + i] = __fdiv_rn(out[OFF_AVG + i], cs);
}

// ======================= launch =======================
extern "C" void kernel_launch(void* const* d_in, const int* in_sizes, int n_in,
                              void* d_out, int out_size) {
    const float* z  = (const float*)d_in[0];
    const float* w  = (const float*)d_in[1];
    const float* ec = (const float*)d_in[2];
    const float* ea = (const float*)d_in[3];
    float* out = (float*)d_out;

    cudaFuncSetAttribute(gemm_score_kernel, cudaFuncAttributeMaxDynamicSharedMemorySize,
                         SMEM_TOTAL);

    norms_kernel<<<NN / 256, 256>>>(z, w);
    split_kernel<<<(NN * DD + 255) / 256, 256>>>(z, w);
    init_kernel<<<(KK * DD + 255) / 256, 256>>>(ea, out);
    dim3 grid(NTILES, NN / BM);   // 64 x 256
    gemm_score_kernel<<<grid, 256, SMEM_TOTAL>>>();
    rescore_kernel<<<(NN * 32 + 255) / 256, 256>>>(z, w, out);
    gather_kernel<<<NN, 256>>>(z, w, out);
    count_kernel<<<KK / 256, 256>>>(ec, out);
    finalize_kernel<<<1, 1024>>>(out);
    embed_kernel<<<(KK * DD + 255) / 256, 256>>>(out);
    (void)in_sizes; (void)n_in; (void)out_size;
}